// round 4
// baseline (speedup 1.0000x reference)
#include <cuda_runtime.h>
#include <cuda_bf16.h>
#include <cstdint>
#include <cstdio>

// ---------------------------------------------------------------------------
// Child-Sum Tree-LSTM over complete 4-ary tree.
// B_FACTOR=4, DEPTH=7, N_NODES=21845, N_INTERNAL=5461, IN=HID=512.
//
// Structure exploited:
//  * wx_iou/wx_f only needed for internal nodes (5461 rows).
//  * children of level l are the contiguous block [offs[l+1], offs[l+2]) ->
//    the f-gate GEMM operand is a plain slice of h (no gather).
//  * level 6 children are leaves (h=c=0): both level-6 GEMMs vanish.
// ---------------------------------------------------------------------------

#define N_NODES     21845
#define N_INTERNAL  5461
#define HID         512
#define IOU3        1536
#define KDIM        512

// Scratch (allocation-free rule: __device__ globals).
__device__ __align__(16) float g_wx_iou[N_INTERNAL * IOU3];   // 33.5 MB
__device__ __align__(16) float g_wx_f  [N_INTERNAL * HID];    // 11.2 MB
__device__ __align__(16) float g_hsum  [1024 * HID];          // max non-leaf level nl=1024
__device__ __align__(16) float g_iou_lin[1024 * IOU3];
__device__ __align__(16) float g_f_lin [4096 * HID];

// ---------------------------------------------------------------------------
// Zero fill (leaves of h and c must be 0; out buffer is poisoned).
// ---------------------------------------------------------------------------
__global__ void zero_kernel(float4* __restrict__ p, int n4) {
    int i = blockIdx.x * blockDim.x + threadIdx.x;
    int stride = gridDim.x * blockDim.x;
    float4 z = make_float4(0.f, 0.f, 0.f, 0.f);
    for (; i < n4; i += stride) p[i] = z;
}

// ---------------------------------------------------------------------------
// SGEMM: C[M,N] = A[M,K] @ B[N,K]^T (+bias[N] if bias != null)
// 128x128 tile, BK=8, 256 threads, 8x8 per-thread microtile.
// N and K must be multiples of 128 / 8 (true here: N in {512,1536}, K=512).
// M is guarded.
// ---------------------------------------------------------------------------
__global__ __launch_bounds__(256) void sgemm_tn(
    const float* __restrict__ A, const float* __restrict__ B,
    const float* __restrict__ bias, float* __restrict__ C,
    int M, int N, int K)
{
    __shared__ float As[8][128];
    __shared__ float Bs[8][128];

    const int tid  = threadIdx.x;
    const int brow = blockIdx.y * 128;
    const int bcol = blockIdx.x * 128;

    const int lr = tid >> 1;          // 0..127 : row within tile for loads
    const int lc = (tid & 1) << 2;    // 0 or 4 : k-offset (float4)

    const int trow = (tid >> 4) << 3; // per-thread output rows base
    const int tcol = (tid & 15) << 3; // per-thread output cols base

    float acc[8][8];
    #pragma unroll
    for (int i = 0; i < 8; i++)
        #pragma unroll
        for (int j = 0; j < 8; j++) acc[i][j] = 0.f;

    const bool a_ok = (brow + lr) < M;
    const float* Aptr = A + (size_t)(brow + lr) * K + lc;
    const float* Bptr = B + (size_t)(bcol + lr) * K + lc;

    for (int k0 = 0; k0 < K; k0 += 8) {
        float4 av = a_ok ? *(const float4*)(Aptr + k0) : make_float4(0,0,0,0);
        float4 bv = *(const float4*)(Bptr + k0);
        As[lc + 0][lr] = av.x;
        As[lc + 1][lr] = av.y;
        As[lc + 2][lr] = av.z;
        As[lc + 3][lr] = av.w;
        Bs[lc + 0][lr] = bv.x;
        Bs[lc + 1][lr] = bv.y;
        Bs[lc + 2][lr] = bv.z;
        Bs[lc + 3][lr] = bv.w;
        __syncthreads();

        #pragma unroll
        for (int kk = 0; kk < 8; kk++) {
            float af[8], bf[8];
            #pragma unroll
            for (int i = 0; i < 8; i++) af[i] = As[kk][trow + i];
            #pragma unroll
            for (int j = 0; j < 8; j++) bf[j] = Bs[kk][tcol + j];
            #pragma unroll
            for (int i = 0; i < 8; i++)
                #pragma unroll
                for (int j = 0; j < 8; j++)
                    acc[i][j] = fmaf(af[i], bf[j], acc[i][j]);
        }
        __syncthreads();
    }

    #pragma unroll
    for (int i = 0; i < 8; i++) {
        int r = brow + trow + i;
        if (r < M) {
            #pragma unroll
            for (int j = 0; j < 8; j++) {
                int cc = bcol + tcol + j;
                float v = acc[i][j];
                if (bias) v += bias[cc];
                C[(size_t)r * N + cc] = v;
            }
        }
    }
}

// ---------------------------------------------------------------------------
// h_sum over the 4 children of each node at this level.
// grid = nl blocks, 512 threads.
// ---------------------------------------------------------------------------
__global__ void reduce4_kernel(const float* __restrict__ h,
                               const int* __restrict__ children,
                               float* __restrict__ hsum, int s)
{
    int m = blockIdx.x;
    int j = threadIdx.x;
    int g = s + m;
    float v = 0.f;
    #pragma unroll
    for (int k = 0; k < 4; k++) {
        int ch = children[g * 4 + k];
        v += h[(size_t)ch * HID + j];
    }
    hsum[(size_t)m * HID + j] = v;
}

// ---------------------------------------------------------------------------
// Gated epilogue. leaf==1: children are leaves (h=c=0) -> skip lin terms
// and f*c_ch terms entirely.
// Split order from jnp.split(iou, 3): i | o | u.
// NOTE: no sigmoid on f (matches reference).
// ---------------------------------------------------------------------------
__global__ void epilogue_kernel(const float* __restrict__ wx_iou,
                                const float* __restrict__ wx_f,
                                const float* __restrict__ iou_lin,
                                const float* __restrict__ f_lin,
                                const int* __restrict__ children,
                                float* __restrict__ h, float* __restrict__ c,
                                int s, int leaf)
{
    int m = blockIdx.x;
    int j = threadIdx.x;
    int g = s + m;

    size_t biou = (size_t)g * IOU3;
    float iv = wx_iou[biou + j];
    float ov = wx_iou[biou + 512 + j];
    float uv = wx_iou[biou + 1024 + j];
    if (!leaf) {
        size_t lb = (size_t)m * IOU3;
        iv += iou_lin[lb + j];
        ov += iou_lin[lb + 512 + j];
        uv += iou_lin[lb + 1024 + j];
    }
    float ig = 1.f / (1.f + expf(-iv));
    float og = 1.f / (1.f + expf(-ov));
    float ug = tanhf(uv);
    float cn = ig * ug;

    if (!leaf) {
        float wf = wx_f[(size_t)g * HID + j];
        #pragma unroll
        for (int k = 0; k < 4; k++) {
            int ch = children[g * 4 + k];
            float f = wf + f_lin[((size_t)(m * 4 + k)) * HID + j];
            cn = fmaf(f, c[(size_t)ch * HID + j], cn);
        }
    }
    h[(size_t)g * HID + j] = og * tanhf(cn);
    c[(size_t)g * HID + j] = cn;
}

// ---------------------------------------------------------------------------
// Host orchestration (graph-capturable: kernel launches only).
// ---------------------------------------------------------------------------
extern "C" void kernel_launch(void* const* d_in, const int* in_sizes, int n_in,
                              void* d_out, int out_size)
{
    const float* x        = (const float*)d_in[0];
    const int*   children = (const int*)  d_in[1];
    const float* W_iou    = (const float*)d_in[2];
    const float* b_iou    = (const float*)d_in[3];
    const float* W_f      = (const float*)d_in[4];
    const float* b_f      = (const float*)d_in[5];
    const float* U_iou    = (const float*)d_in[6];
    const float* U_f      = (const float*)d_in[7];

    float* h = (float*)d_out;
    float* c = h + (size_t)N_NODES * HID;

    // Scratch pointers (symbol lookup is not a stream op; capture-safe).
    float *wx_iou, *wx_f, *hsum, *iou_lin, *f_lin;
    cudaGetSymbolAddress((void**)&wx_iou,  g_wx_iou);
    cudaGetSymbolAddress((void**)&wx_f,    g_wx_f);
    cudaGetSymbolAddress((void**)&hsum,    g_hsum);
    cudaGetSymbolAddress((void**)&iou_lin, g_iou_lin);
    cudaGetSymbolAddress((void**)&f_lin,   g_f_lin);

    // 1. zero h,c (leaves stay zero; internal nodes overwritten below)
    {
        int n4 = (2 * N_NODES * HID) / 4;
        zero_kernel<<<2048, 256>>>((float4*)d_out, n4);
    }

    // 2. precompute wx for internal nodes only
    {
        dim3 g1(IOU3 / 128, (N_INTERNAL + 127) / 128);
        sgemm_tn<<<g1, 256>>>(x, W_iou, b_iou, wx_iou, N_INTERNAL, IOU3, KDIM);
        dim3 g2(HID / 128, (N_INTERNAL + 127) / 128);
        sgemm_tn<<<g2, 256>>>(x, W_f, b_f, wx_f, N_INTERNAL, HID, KDIM);
    }

    // Level offsets: offs[l] = (4^l - 1)/3
    static const int offs[9] = {0, 1, 5, 21, 85, 341, 1365, 5461, 21845};

    // 3. level loop, bottom-up
    for (int l = 6; l >= 0; --l) {
        int s  = offs[l];
        int nl = offs[l + 1] - s;
        int cs = offs[l + 1];  // children block start (contiguous)

        if (l == 6) {
            // children are leaves: all GEMMs are zero -> pure epilogue
            epilogue_kernel<<<nl, HID>>>(wx_iou, wx_f, nullptr, nullptr,
                                         children, h, c, s, /*leaf=*/1);
        } else {
            reduce4_kernel<<<nl, HID>>>(h, children, hsum, s);

            dim3 g1(IOU3 / 128, (nl + 127) / 128);
            sgemm_tn<<<g1, 256>>>(hsum, U_iou, nullptr, iou_lin, nl, IOU3, KDIM);

            int mf = 4 * nl;
            dim3 g2(HID / 128, (mf + 127) / 128);
            sgemm_tn<<<g2, 256>>>(h + (size_t)cs * HID, U_f, nullptr, f_lin,
                                  mf, HID, KDIM);

            epilogue_kernel<<<nl, HID>>>(wx_iou, wx_f, iou_lin, f_lin,
                                         children, h, c, s, /*leaf=*/0);
        }
    }
}

// round 8
// speedup vs baseline: 2.5152x; 2.5152x over previous
#include <cuda_runtime.h>
#include <cuda_bf16.h>
#include <cstdint>
#include <cstdio>

// ---------------------------------------------------------------------------
// Child-Sum Tree-LSTM, complete 4-ary tree. B=4, DEPTH=7.
// N_NODES=21845, N_INTERNAL=5461, HID=512, IOU3=1536, K=512.
//
// Round-7: tcgen05 is NOT available (harness compiles PTX for plain sm_103,
// which rejects all tcgen05/*a features). Use warp-level mma.sync bf16 HMMA
// (sm_80+ path) with 2-term hi/lo split for fp32-class accuracy, cp.async
// double-buffered smem pipeline, ldmatrix fragments.
// ---------------------------------------------------------------------------

#define N_NODES     21845
#define N_INTERNAL  5461
#define HID         512
#define IOU3        1536
#define KDIM        512

// ---------------- scratch (__device__ globals; allocation-free rule) -------
__device__ __align__(16) float g_wx_iou [N_INTERNAL * IOU3];
__device__ __align__(16) float g_wx_f   [N_INTERNAL * HID];
__device__ __align__(16) float g_iou_lin[1024 * IOU3];
__device__ __align__(16) float g_f_lin  [4096 * HID];

__device__ __align__(16) __nv_bfloat16 g_x_hi [N_INTERNAL * KDIM];
__device__ __align__(16) __nv_bfloat16 g_x_lo [N_INTERNAL * KDIM];
__device__ __align__(16) __nv_bfloat16 g_h_hi [N_INTERNAL * HID];
__device__ __align__(16) __nv_bfloat16 g_h_lo [N_INTERNAL * HID];
__device__ __align__(16) __nv_bfloat16 g_hs_hi[1024 * HID];
__device__ __align__(16) __nv_bfloat16 g_hs_lo[1024 * HID];

__device__ __align__(16) __nv_bfloat16 g_Wiou_hi[IOU3 * KDIM];
__device__ __align__(16) __nv_bfloat16 g_Wiou_lo[IOU3 * KDIM];
__device__ __align__(16) __nv_bfloat16 g_Wf_hi  [HID * KDIM];
__device__ __align__(16) __nv_bfloat16 g_Wf_lo  [HID * KDIM];
__device__ __align__(16) __nv_bfloat16 g_Uiou_hi[IOU3 * HID];
__device__ __align__(16) __nv_bfloat16 g_Uiou_lo[IOU3 * HID];
__device__ __align__(16) __nv_bfloat16 g_Uf_hi  [HID * HID];
__device__ __align__(16) __nv_bfloat16 g_Uf_lo  [HID * HID];

// ---------------------------------------------------------------------------
// PTX helpers (all plain-sm_103-legal: ldmatrix, mma.sync bf16, cp.async)
// ---------------------------------------------------------------------------
__device__ __forceinline__ uint32_t smem_u32(const void* ptr) {
    uint32_t a;
    asm("{ .reg .u64 t; cvta.to.shared.u64 t, %1; cvt.u32.u64 %0, t; }"
        : "=r"(a) : "l"(ptr));
    return a;
}

__device__ __forceinline__ void cp16(uint32_t s, const void* g, bool valid) {
    int sz = valid ? 16 : 0;
    asm volatile("cp.async.cg.shared.global [%0], [%1], 16, %2;"
                 :: "r"(s), "l"(g), "r"(sz));
}
#define CP_COMMIT() asm volatile("cp.async.commit_group;")
template <int N>
__device__ __forceinline__ void cp_wait() {
    asm volatile("cp.async.wait_group %0;" :: "n"(N));
}

#define LDMX4(r, addr) \
    asm volatile("ldmatrix.sync.aligned.m8n8.x4.shared.b16 {%0,%1,%2,%3}, [%4];" \
        : "=r"((r)[0]), "=r"((r)[1]), "=r"((r)[2]), "=r"((r)[3]) : "r"(addr))

#define MMA_BF16(d, a, b0v, b1v) \
    asm volatile("mma.sync.aligned.m16n8k16.row.col.f32.bf16.bf16.f32 " \
        "{%0,%1,%2,%3}, {%4,%5,%6,%7}, {%8,%9}, {%0,%1,%2,%3};" \
        : "+f"((d)[0]), "+f"((d)[1]), "+f"((d)[2]), "+f"((d)[3]) \
        : "r"((a)[0]), "r"((a)[1]), "r"((a)[2]), "r"((a)[3]), \
          "r"(b0v), "r"(b1v))

// ---------------------------------------------------------------------------
// GEMM: C[M,N] = (Ahi+Alo)[M,512] @ (Bhi+Blo)[N,512]^T (+bias)
//   3-term split: Ahi*Bhi + Ahi*Blo + Alo*Bhi   (lo*lo dropped, ~2^-18 rel)
// CTA tile 128x128, K-chunk 32, 8 warps (warp tile 64x32), 2-stage cp.async.
// Smem rows padded to 40 bf16 (80B) -> conflict-free ldmatrix.
// ---------------------------------------------------------------------------
#define ROWB        80        // padded row stride in bytes (40 bf16)
#define TILE_BYTES  10240     // 128 rows * 80B
#define OFF_AH      0
#define OFF_AL      10240
#define OFF_BH      20480
#define OFF_BL      30720
#define STAGE_BYTES 40960
#define GEMM_SMEM   (2 * STAGE_BYTES)   // 81920

__global__ __launch_bounds__(256) void gemm_bf16_split(
    const __nv_bfloat16* __restrict__ Ahi, const __nv_bfloat16* __restrict__ Alo,
    const __nv_bfloat16* __restrict__ Bhi, const __nv_bfloat16* __restrict__ Blo,
    const float* __restrict__ bias, float* __restrict__ C, int M, int N)
{
    extern __shared__ char smem[];
    const uint32_t sb = smem_u32(smem);

    const int tid  = threadIdx.x;
    const int wid  = tid >> 5;
    const int lane = tid & 31;
    const int wm   = wid >> 2;      // 0..1  (64-row warp tile)
    const int wn   = wid & 3;       // 0..3  (32-col warp tile)
    const int brow = blockIdx.y * 128;
    const int bcol = blockIdx.x * 128;

    // ---- loader mapping: thread -> (row, 16-elem col group) ----
    const int srow = tid >> 1;            // 0..127
    const int scol = (tid & 1) * 16;      // 0 or 16 (elements)
    const uint32_t soff = (uint32_t)(srow * ROWB + scol * 2);
    const bool a_ok = (brow + srow) < M;

    const __nv_bfloat16* gAh = Ahi + (size_t)(brow + srow) * KDIM + scol;
    const __nv_bfloat16* gAl = Alo + (size_t)(brow + srow) * KDIM + scol;
    const __nv_bfloat16* gBh = Bhi + (size_t)(bcol + srow) * KDIM + scol;
    const __nv_bfloat16* gBl = Blo + (size_t)(bcol + srow) * KDIM + scol;

    auto prefetch = [&](int chunk, int s) {
        const uint32_t base = sb + (uint32_t)s * STAGE_BYTES + soff;
        const int k0 = chunk * 32;
        cp16(base + OFF_AH,      gAh + k0,     a_ok);
        cp16(base + OFF_AH + 16, gAh + k0 + 8, a_ok);
        cp16(base + OFF_AL,      gAl + k0,     a_ok);
        cp16(base + OFF_AL + 16, gAl + k0 + 8, a_ok);
        cp16(base + OFF_BH,      gBh + k0,     true);
        cp16(base + OFF_BH + 16, gBh + k0 + 8, true);
        cp16(base + OFF_BL,      gBl + k0,     true);
        cp16(base + OFF_BL + 16, gBl + k0 + 8, true);
        CP_COMMIT();
    };

    float acc[4][4][4];
    #pragma unroll
    for (int i = 0; i < 4; i++)
        #pragma unroll
        for (int j = 0; j < 4; j++)
            #pragma unroll
            for (int k = 0; k < 4; k++) acc[i][j][k] = 0.f;

    // fragment smem address pieces (ldmatrix x4: rows lane&15, col-half lane>>4)
    const uint32_t fr_row = (uint32_t)(lane & 15);
    const uint32_t fr_kof = (uint32_t)((lane >> 4) * 8);

    prefetch(0, 0);

    const int NCH = KDIM / 32;   // 16
    for (int ch = 0; ch < NCH; ch++) {
        const int s = ch & 1;
        if (ch + 1 < NCH) { prefetch(ch + 1, s ^ 1); cp_wait<1>(); }
        else              { cp_wait<0>(); }
        __syncthreads();

        const uint32_t base = sb + (uint32_t)s * STAGE_BYTES;
        #pragma unroll
        for (int kt = 0; kt < 2; kt++) {
            const uint32_t kbyte = (uint32_t)((kt * 16 + fr_kof) * 2);

            uint32_t ah[4][4], al[4][4];
            #pragma unroll
            for (int mt = 0; mt < 4; mt++) {
                uint32_t row = (uint32_t)(wm * 64 + mt * 16) + fr_row;
                uint32_t ad = base + OFF_AH + row * ROWB + kbyte;
                LDMX4(ah[mt], ad);
                LDMX4(al[mt], ad + (OFF_AL - OFF_AH));
            }
            uint32_t bh[2][4], bl[2][4];
            #pragma unroll
            for (int nc = 0; nc < 2; nc++) {
                uint32_t row = (uint32_t)(wn * 32 + nc * 16) + fr_row;
                uint32_t ad = base + OFF_BH + row * ROWB + kbyte;
                LDMX4(bh[nc], ad);
                LDMX4(bl[nc], ad + (OFF_BL - OFF_BH));
            }
            #pragma unroll
            for (int mt = 0; mt < 4; mt++) {
                #pragma unroll
                for (int nc = 0; nc < 2; nc++) {
                    #pragma unroll
                    for (int sub = 0; sub < 2; sub++) {
                        float* d = acc[mt][nc * 2 + sub];
                        MMA_BF16(d, ah[mt], bh[nc][sub], bh[nc][sub + 2]);
                        MMA_BF16(d, ah[mt], bl[nc][sub], bl[nc][sub + 2]);
                        MMA_BF16(d, al[mt], bh[nc][sub], bh[nc][sub + 2]);
                    }
                }
            }
        }
        __syncthreads();   // all warps done with stage s before it is refilled
    }

    // ---- epilogue: D fragment layout m16n8: (lane>>2, 2*(lane&3)) ----
    const int erow = lane >> 2;
    const int ecol = (lane & 3) * 2;
    #pragma unroll
    for (int mt = 0; mt < 4; mt++) {
        const int r0 = brow + wm * 64 + mt * 16 + erow;
        #pragma unroll
        for (int nt = 0; nt < 4; nt++) {
            const int cc = bcol + wn * 32 + nt * 8 + ecol;
            float b0 = 0.f, b1 = 0.f;
            if (bias) { b0 = bias[cc]; b1 = bias[cc + 1]; }
            if (r0 < M) {
                float2 v = make_float2(acc[mt][nt][0] + b0, acc[mt][nt][1] + b1);
                *(float2*)(C + (size_t)r0 * N + cc) = v;
            }
            if (r0 + 8 < M) {
                float2 v = make_float2(acc[mt][nt][2] + b0, acc[mt][nt][3] + b1);
                *(float2*)(C + (size_t)(r0 + 8) * N + cc) = v;
            }
        }
    }
}

// ---------------------------------------------------------------------------
// fp32 -> bf16 hi/lo split
// ---------------------------------------------------------------------------
__global__ void split_kernel(const float* __restrict__ src,
                             __nv_bfloat16* __restrict__ hi,
                             __nv_bfloat16* __restrict__ lo, int n)
{
    int i = blockIdx.x * blockDim.x + threadIdx.x;
    int st = gridDim.x * blockDim.x;
    for (; i < n; i += st) {
        float v = src[i];
        __nv_bfloat16 h = __float2bfloat16(v);
        hi[i] = h;
        lo[i] = __float2bfloat16(v - __bfloat162float(h));
    }
}

// ---------------------------------------------------------------------------
// zero fill
// ---------------------------------------------------------------------------
__global__ void zero_kernel(float4* __restrict__ p, int n4) {
    int i = blockIdx.x * blockDim.x + threadIdx.x;
    int st = gridDim.x * blockDim.x;
    float4 z = make_float4(0.f, 0.f, 0.f, 0.f);
    for (; i < n4; i += st) p[i] = z;
}

// ---------------------------------------------------------------------------
// h_sum over 4 children -> bf16 hi/lo directly
// ---------------------------------------------------------------------------
__global__ void reduce4_split_kernel(const float* __restrict__ h,
                                     const int* __restrict__ children,
                                     __nv_bfloat16* __restrict__ hs_hi,
                                     __nv_bfloat16* __restrict__ hs_lo, int s)
{
    int m = blockIdx.x, j = threadIdx.x, g = s + m;
    float v = 0.f;
    #pragma unroll
    for (int k = 0; k < 4; k++) {
        int ch = children[g * 4 + k];
        v += h[(size_t)ch * HID + j];
    }
    __nv_bfloat16 hh = __float2bfloat16(v);
    hs_hi[(size_t)m * HID + j] = hh;
    hs_lo[(size_t)m * HID + j] = __float2bfloat16(v - __bfloat162float(hh));
}

// ---------------------------------------------------------------------------
// Gated epilogue (also emits h in bf16 hi/lo for the next level's f-GEMM).
// i|o|u split order; NO sigmoid on f (matches reference).
// ---------------------------------------------------------------------------
__global__ void epilogue_kernel(const float* __restrict__ wx_iou,
                                const float* __restrict__ wx_f,
                                const float* __restrict__ iou_lin,
                                const float* __restrict__ f_lin,
                                const int* __restrict__ children,
                                float* __restrict__ h, float* __restrict__ c,
                                __nv_bfloat16* __restrict__ h_hi,
                                __nv_bfloat16* __restrict__ h_lo,
                                int s, int leaf)
{
    int m = blockIdx.x, j = threadIdx.x, g = s + m;

    size_t biou = (size_t)g * IOU3;
    float iv = wx_iou[biou + j];
    float ov = wx_iou[biou + 512 + j];
    float uv = wx_iou[biou + 1024 + j];
    if (!leaf) {
        size_t lb = (size_t)m * IOU3;
        iv += iou_lin[lb + j];
        ov += iou_lin[lb + 512 + j];
        uv += iou_lin[lb + 1024 + j];
    }
    float ig = 1.f / (1.f + expf(-iv));
    float og = 1.f / (1.f + expf(-ov));
    float ug = tanhf(uv);
    float cn = ig * ug;

    if (!leaf) {
        float wf = wx_f[(size_t)g * HID + j];
        #pragma unroll
        for (int k = 0; k < 4; k++) {
            int ch = children[g * 4 + k];
            float f = wf + f_lin[((size_t)(m * 4 + k)) * HID + j];
            cn = fmaf(f, c[(size_t)ch * HID + j], cn);
        }
    }
    float hv = og * tanhf(cn);
    h[(size_t)g * HID + j] = hv;
    c[(size_t)g * HID + j] = cn;
    __nv_bfloat16 hh = __float2bfloat16(hv);
    h_hi[(size_t)g * HID + j] = hh;
    h_lo[(size_t)g * HID + j] = __float2bfloat16(hv - __bfloat162float(hh));
}

// ---------------------------------------------------------------------------
// Host orchestration (graph-capturable: kernel launches only).
// ---------------------------------------------------------------------------
extern "C" void kernel_launch(void* const* d_in, const int* in_sizes, int n_in,
                              void* d_out, int out_size)
{
    const float* x        = (const float*)d_in[0];
    const int*   children = (const int*)  d_in[1];
    const float* W_iou    = (const float*)d_in[2];
    const float* b_iou    = (const float*)d_in[3];
    const float* W_f      = (const float*)d_in[4];
    const float* b_f      = (const float*)d_in[5];
    const float* U_iou    = (const float*)d_in[6];
    const float* U_f      = (const float*)d_in[7];

    float* h = (float*)d_out;
    float* c = h + (size_t)N_NODES * HID;

    static bool attr_set = false;
    if (!attr_set) {
        cudaFuncSetAttribute(gemm_bf16_split,
                             cudaFuncAttributeMaxDynamicSharedMemorySize,
                             GEMM_SMEM);
        attr_set = true;
    }

    float *wx_iou, *wx_f, *iou_lin, *f_lin;
    __nv_bfloat16 *x_hi, *x_lo, *h_hi, *h_lo, *hs_hi, *hs_lo;
    __nv_bfloat16 *Wiou_hi, *Wiou_lo, *Wf_hi, *Wf_lo, *Uiou_hi, *Uiou_lo, *Uf_hi, *Uf_lo;
    cudaGetSymbolAddress((void**)&wx_iou,  g_wx_iou);
    cudaGetSymbolAddress((void**)&wx_f,    g_wx_f);
    cudaGetSymbolAddress((void**)&iou_lin, g_iou_lin);
    cudaGetSymbolAddress((void**)&f_lin,   g_f_lin);
    cudaGetSymbolAddress((void**)&x_hi,    g_x_hi);
    cudaGetSymbolAddress((void**)&x_lo,    g_x_lo);
    cudaGetSymbolAddress((void**)&h_hi,    g_h_hi);
    cudaGetSymbolAddress((void**)&h_lo,    g_h_lo);
    cudaGetSymbolAddress((void**)&hs_hi,   g_hs_hi);
    cudaGetSymbolAddress((void**)&hs_lo,   g_hs_lo);
    cudaGetSymbolAddress((void**)&Wiou_hi, g_Wiou_hi);
    cudaGetSymbolAddress((void**)&Wiou_lo, g_Wiou_lo);
    cudaGetSymbolAddress((void**)&Wf_hi,   g_Wf_hi);
    cudaGetSymbolAddress((void**)&Wf_lo,   g_Wf_lo);
    cudaGetSymbolAddress((void**)&Uiou_hi, g_Uiou_hi);
    cudaGetSymbolAddress((void**)&Uiou_lo, g_Uiou_lo);
    cudaGetSymbolAddress((void**)&Uf_hi,   g_Uf_hi);
    cudaGetSymbolAddress((void**)&Uf_lo,   g_Uf_lo);

    // 1. zero leaf rows of h and c (internal rows fully overwritten)
    {
        const size_t leafBase = (size_t)N_INTERNAL * HID;
        const int n4 = (N_NODES - N_INTERNAL) * HID / 4;
        zero_kernel<<<1024, 256>>>((float4*)(h + leafBase), n4);
        zero_kernel<<<1024, 256>>>((float4*)(c + leafBase), n4);
    }

    // 2. bf16 hi/lo splits (weights + internal x rows)
    split_kernel<<<2048, 256>>>(W_iou, Wiou_hi, Wiou_lo, IOU3 * KDIM);
    split_kernel<<<1024, 256>>>(W_f,   Wf_hi,   Wf_lo,   HID * KDIM);
    split_kernel<<<2048, 256>>>(U_iou, Uiou_hi, Uiou_lo, IOU3 * HID);
    split_kernel<<<1024, 256>>>(U_f,   Uf_hi,   Uf_lo,   HID * HID);
    split_kernel<<<4096, 256>>>(x,     x_hi,    x_lo,    N_INTERNAL * KDIM);

    // 3. precompute wx for internal nodes
    {
        dim3 g1(IOU3 / 128, (N_INTERNAL + 127) / 128);
        gemm_bf16_split<<<g1, 256, GEMM_SMEM>>>(x_hi, x_lo, Wiou_hi, Wiou_lo,
                                                b_iou, wx_iou, N_INTERNAL, IOU3);
        dim3 g2(HID / 128, (N_INTERNAL + 127) / 128);
        gemm_bf16_split<<<g2, 256, GEMM_SMEM>>>(x_hi, x_lo, Wf_hi, Wf_lo,
                                                b_f, wx_f, N_INTERNAL, HID);
    }

    static const int offs[9] = {0, 1, 5, 21, 85, 341, 1365, 5461, 21845};

    // 4. level 6: children are leaves -> pure pointwise
    {
        int s = offs[6], nl = offs[7] - offs[6];
        epilogue_kernel<<<nl, HID>>>(wx_iou, wx_f, nullptr, nullptr, children,
                                     h, c, h_hi, h_lo, s, 1);
    }

    // 5. levels 5..0
    for (int l = 5; l >= 0; --l) {
        int s  = offs[l];
        int nl = offs[l + 1] - s;
        int cs = offs[l + 1];

        reduce4_split_kernel<<<nl, HID>>>(h, children, hs_hi, hs_lo, s);

        dim3 g1(IOU3 / 128, (nl + 127) / 128);
        gemm_bf16_split<<<g1, 256, GEMM_SMEM>>>(hs_hi, hs_lo, Uiou_hi, Uiou_lo,
                                                nullptr, iou_lin, nl, IOU3);

        int mf = 4 * nl;
        dim3 g2(HID / 128, (mf + 127) / 128);
        gemm_bf16_split<<<g2, 256, GEMM_SMEM>>>(h_hi + (size_t)cs * HID,
                                                h_lo + (size_t)cs * HID,
                                                Uf_hi, Uf_lo, nullptr, f_lin,
                                                mf, HID);

        epilogue_kernel<<<nl, HID>>>(wx_iou, wx_f, iou_lin, f_lin, children,
                                     h, c, h_hi, h_lo, s, 0);
    }
}

// round 13
// speedup vs baseline: 3.6634x; 1.4565x over previous
#include <cuda_runtime.h>
#include <cuda_bf16.h>
#include <cstdint>
#include <cstdio>

// ---------------------------------------------------------------------------
// Child-Sum Tree-LSTM, complete 4-ary tree. B=4, DEPTH=7.
// N_NODES=21845, N_INTERNAL=5461, HID=512, IOU3=1536, K=512.
//
// R13: R9 structure with FIXED scratch sizes. GEMM levels are 5 (nl=1024,
// mf=4096) and 4 (nl=256, mf=1024); R9 sized partial/hsum buffers one level
// too small -> overflow -> rel_err 0.15. Sizes now match level 5.
// ---------------------------------------------------------------------------

#define N_NODES     21845
#define N_INTERNAL  5461
#define HID         512
#define IOU3        1536
#define KDIM        512
#define KSPLIT      4
#define PS_IOU      (1024 * 1536)    // level-5 iou partial: M up to 1024
#define PS_F        (4096 * 512)     // level-5 f partial:   M up to 4096

// ---------------- scratch (__device__ globals; allocation-free rule) -------
__device__ __align__(16) float g_wx      [N_INTERNAL * 2048];     // [iou|f]
__device__ __align__(16) float g_iou_part[KSPLIT * PS_IOU];
__device__ __align__(16) float g_f_part  [KSPLIT * PS_F];
__device__ __align__(16) float g_bias    [2048];

__device__ __align__(16) __nv_bfloat16 g_x_hi [N_INTERNAL * KDIM];
__device__ __align__(16) __nv_bfloat16 g_x_lo [N_INTERNAL * KDIM];
__device__ __align__(16) __nv_bfloat16 g_h_hi [N_INTERNAL * HID];
__device__ __align__(16) __nv_bfloat16 g_h_lo [N_INTERNAL * HID];
__device__ __align__(16) __nv_bfloat16 g_hs_hi[1024 * HID];
__device__ __align__(16) __nv_bfloat16 g_hs_lo[1024 * HID];

__device__ __align__(16) __nv_bfloat16 g_Wcat_hi[2048 * KDIM];    // [W_iou;W_f]
__device__ __align__(16) __nv_bfloat16 g_Wcat_lo[2048 * KDIM];
__device__ __align__(16) __nv_bfloat16 g_Uiou_hi[IOU3 * HID];
__device__ __align__(16) __nv_bfloat16 g_Uiou_lo[IOU3 * HID];
__device__ __align__(16) __nv_bfloat16 g_Uf_hi  [HID * HID];
__device__ __align__(16) __nv_bfloat16 g_Uf_lo  [HID * HID];

// ---------------------------------------------------------------------------
// PTX helpers (plain-sm_103-legal)
// ---------------------------------------------------------------------------
__device__ __forceinline__ uint32_t smem_u32(const void* ptr) {
    uint32_t a;
    asm("{ .reg .u64 t; cvta.to.shared.u64 t, %1; cvt.u32.u64 %0, t; }"
        : "=r"(a) : "l"(ptr));
    return a;
}
__device__ __forceinline__ void cp16(uint32_t s, const void* g, bool valid) {
    int sz = valid ? 16 : 0;
    asm volatile("cp.async.cg.shared.global [%0], [%1], 16, %2;"
                 :: "r"(s), "l"(g), "r"(sz));
}
#define CP_COMMIT() asm volatile("cp.async.commit_group;")
template <int N>
__device__ __forceinline__ void cp_wait() {
    asm volatile("cp.async.wait_group %0;" :: "n"(N));
}
#define LDMX4(r, addr) \
    asm volatile("ldmatrix.sync.aligned.m8n8.x4.shared.b16 {%0,%1,%2,%3}, [%4];" \
        : "=r"((r)[0]), "=r"((r)[1]), "=r"((r)[2]), "=r"((r)[3]) : "r"(addr))
#define MMA_BF16(d, a, b0v, b1v) \
    asm volatile("mma.sync.aligned.m16n8k16.row.col.f32.bf16.bf16.f32 " \
        "{%0,%1,%2,%3}, {%4,%5,%6,%7}, {%8,%9}, {%0,%1,%2,%3};" \
        : "+f"((d)[0]), "+f"((d)[1]), "+f"((d)[2]), "+f"((d)[3]) \
        : "r"((a)[0]), "r"((a)[1]), "r"((a)[2]), "r"((a)[3]), \
          "r"(b0v), "r"(b1v))

// ---------------------------------------------------------------------------
// GEMM: C[M,N] (+bias) = (Ahi+Alo)[M,512] @ (Bhi+Blo)[N,512]^T, 3-term split.
// CTA 128x128, 8 warps (64x32), K-chunk 32, 3-stage cp.async pipeline.
// blockIdx.z = K-split; split z handles chunks [z*cpz, (z+1)*cpz) and writes
// C + z*zstride (zstride=0 for unsplit launches).
// ---------------------------------------------------------------------------
#define ROWB        80
#define OFF_AH      0
#define OFF_AL      10240
#define OFF_BH      20480
#define OFF_BL      30720
#define STAGE_BYTES 40960
#define GEMM_SMEM   (3 * STAGE_BYTES)    // 122880

__global__ __launch_bounds__(256) void gemm_bf16_split(
    const __nv_bfloat16* __restrict__ Ahi, const __nv_bfloat16* __restrict__ Alo,
    const __nv_bfloat16* __restrict__ Bhi, const __nv_bfloat16* __restrict__ Blo,
    const float* __restrict__ bias, float* __restrict__ C, int M, int N,
    int cpz, size_t zstride)
{
    extern __shared__ char smem[];
    const uint32_t sb = smem_u32(smem);

    const int tid  = threadIdx.x;
    const int wid  = tid >> 5;
    const int lane = tid & 31;
    const int wm   = wid >> 2;
    const int wn   = wid & 3;
    const int brow = blockIdx.y * 128;
    const int bcol = blockIdx.x * 128;
    const int c0   = blockIdx.z * cpz;

    const int srow = tid >> 1;
    const int scol = (tid & 1) * 16;
    const uint32_t soff = (uint32_t)(srow * ROWB + scol * 2);
    const bool a_ok = (brow + srow) < M;

    const __nv_bfloat16* gAh = Ahi + (size_t)(brow + srow) * KDIM + scol;
    const __nv_bfloat16* gAl = Alo + (size_t)(brow + srow) * KDIM + scol;
    const __nv_bfloat16* gBh = Bhi + (size_t)(bcol + srow) * KDIM + scol;
    const __nv_bfloat16* gBl = Blo + (size_t)(bcol + srow) * KDIM + scol;

    auto prefetch = [&](int chunk, int st) {
        const uint32_t base = sb + (uint32_t)st * STAGE_BYTES + soff;
        const int k0 = chunk * 32;
        cp16(base + OFF_AH,      gAh + k0,     a_ok);
        cp16(base + OFF_AH + 16, gAh + k0 + 8, a_ok);
        cp16(base + OFF_AL,      gAl + k0,     a_ok);
        cp16(base + OFF_AL + 16, gAl + k0 + 8, a_ok);
        cp16(base + OFF_BH,      gBh + k0,     true);
        cp16(base + OFF_BH + 16, gBh + k0 + 8, true);
        cp16(base + OFF_BL,      gBl + k0,     true);
        cp16(base + OFF_BL + 16, gBl + k0 + 8, true);
        CP_COMMIT();
    };

    float acc[4][4][4];
    #pragma unroll
    for (int i = 0; i < 4; i++)
        #pragma unroll
        for (int j = 0; j < 4; j++)
            #pragma unroll
            for (int k = 0; k < 4; k++) acc[i][j][k] = 0.f;

    const uint32_t fr_row = (uint32_t)(lane & 15);
    const uint32_t fr_kof = (uint32_t)((lane >> 4) * 8);

    prefetch(c0, 0);
    if (cpz > 1) prefetch(c0 + 1, 1);

    for (int i = 0; i < cpz; i++) {
        if (i + 1 < cpz) cp_wait<1>(); else cp_wait<0>();
        __syncthreads();
        if (i + 2 < cpz) prefetch(c0 + i + 2, (i + 2) % 3);

        const uint32_t base = sb + (uint32_t)(i % 3) * STAGE_BYTES;
        #pragma unroll
        for (int kt = 0; kt < 2; kt++) {
            const uint32_t kbyte = (uint32_t)((kt * 16 + fr_kof) * 2);
            uint32_t ah[4][4], al[4][4];
            #pragma unroll
            for (int mt = 0; mt < 4; mt++) {
                uint32_t row = (uint32_t)(wm * 64 + mt * 16) + fr_row;
                uint32_t ad = base + OFF_AH + row * ROWB + kbyte;
                LDMX4(ah[mt], ad);
                LDMX4(al[mt], ad + (OFF_AL - OFF_AH));
            }
            uint32_t bh[2][4], bl[2][4];
            #pragma unroll
            for (int nc = 0; nc < 2; nc++) {
                uint32_t row = (uint32_t)(wn * 32 + nc * 16) + fr_row;
                uint32_t ad = base + OFF_BH + row * ROWB + kbyte;
                LDMX4(bh[nc], ad);
                LDMX4(bl[nc], ad + (OFF_BL - OFF_BH));
            }
            #pragma unroll
            for (int mt = 0; mt < 4; mt++)
                #pragma unroll
                for (int nc = 0; nc < 2; nc++)
                    #pragma unroll
                    for (int sub = 0; sub < 2; sub++) {
                        float* d = acc[mt][nc * 2 + sub];
                        MMA_BF16(d, ah[mt], bh[nc][sub], bh[nc][sub + 2]);
                        MMA_BF16(d, ah[mt], bl[nc][sub], bl[nc][sub + 2]);
                        MMA_BF16(d, al[mt], bh[nc][sub], bh[nc][sub + 2]);
                    }
        }
    }

    float* Cz = C + (size_t)blockIdx.z * zstride;
    const int erow = lane >> 2;
    const int ecol = (lane & 3) * 2;
    #pragma unroll
    for (int mt = 0; mt < 4; mt++) {
        const int r0 = brow + wm * 64 + mt * 16 + erow;
        #pragma unroll
        for (int nt = 0; nt < 4; nt++) {
            const int cc = bcol + wn * 32 + nt * 8 + ecol;
            float b0 = 0.f, b1 = 0.f;
            if (bias) { b0 = bias[cc]; b1 = bias[cc + 1]; }
            if (r0 < M) {
                float2 v = make_float2(acc[mt][nt][0] + b0, acc[mt][nt][1] + b1);
                *(float2*)(Cz + (size_t)r0 * N + cc) = v;
            }
            if (r0 + 8 < M) {
                float2 v = make_float2(acc[mt][nt][2] + b0, acc[mt][nt][3] + b1);
                *(float2*)(Cz + (size_t)(r0 + 8) * N + cc) = v;
            }
        }
    }
}

// ---------------------------------------------------------------------------
// fp32 -> bf16 hi/lo split ; zero ; bias concat
// ---------------------------------------------------------------------------
__global__ void split_kernel(const float* __restrict__ src,
                             __nv_bfloat16* __restrict__ hi,
                             __nv_bfloat16* __restrict__ lo, int n)
{
    int i = blockIdx.x * blockDim.x + threadIdx.x;
    int st = gridDim.x * blockDim.x;
    for (; i < n; i += st) {
        float v = src[i];
        __nv_bfloat16 h = __float2bfloat16(v);
        hi[i] = h;
        lo[i] = __float2bfloat16(v - __bfloat162float(h));
    }
}
__global__ void zero_kernel(float4* __restrict__ p, int n4) {
    int i = blockIdx.x * blockDim.x + threadIdx.x;
    int st = gridDim.x * blockDim.x;
    float4 z = make_float4(0.f, 0.f, 0.f, 0.f);
    for (; i < n4; i += st) p[i] = z;
}
__global__ void concat_bias_kernel(const float* __restrict__ b_iou,
                                   const float* __restrict__ b_f,
                                   float* __restrict__ out)
{
    int i = blockIdx.x * blockDim.x + threadIdx.x;
    if (i < 2048) out[i] = (i < 1536) ? b_iou[i] : b_f[i - 1536];
}

// ---------------------------------------------------------------------------
// h_sum over 4 children -> bf16 hi/lo
// ---------------------------------------------------------------------------
__global__ void reduce4_split_kernel(const float* __restrict__ h,
                                     const int* __restrict__ children,
                                     __nv_bfloat16* __restrict__ hs_hi,
                                     __nv_bfloat16* __restrict__ hs_lo, int s)
{
    int m = blockIdx.x, j = threadIdx.x, g = s + m;
    float v = 0.f;
    #pragma unroll
    for (int k = 0; k < 4; k++) {
        int ch = children[g * 4 + k];
        v += h[(size_t)ch * HID + j];
    }
    __nv_bfloat16 hh = __float2bfloat16(v);
    hs_hi[(size_t)m * HID + j] = hh;
    hs_lo[(size_t)m * HID + j] = __float2bfloat16(v - __bfloat162float(hh));
}

// ---------------------------------------------------------------------------
// Gated epilogue (levels 6,5,4). Sums KSPLIT GEMM partials when !leaf.
// wx layout: row g, cols [0:512)=i, [512:1024)=o, [1024:1536)=u, [1536:2048)=wf.
// NO sigmoid on f (matches reference). Writes h,c and bf16 hi/lo of h.
// ---------------------------------------------------------------------------
__global__ void epilogue_kernel(const float* __restrict__ wx,
                                const float* __restrict__ iou_part,
                                const float* __restrict__ f_part,
                                const int* __restrict__ children,
                                float* __restrict__ h, float* __restrict__ c,
                                __nv_bfloat16* __restrict__ h_hi,
                                __nv_bfloat16* __restrict__ h_lo,
                                int s, int leaf)
{
    int m = blockIdx.x, j = threadIdx.x, g = s + m;

    size_t wrow = (size_t)g * 2048;
    float iv = wx[wrow + j];
    float ov = wx[wrow + 512 + j];
    float uv = wx[wrow + 1024 + j];
    if (!leaf) {
        size_t lb = (size_t)m * IOU3 + j;
        #pragma unroll
        for (int z = 0; z < KSPLIT; z++) {
            const float* p = iou_part + (size_t)z * PS_IOU + lb;
            iv += p[0]; ov += p[512]; uv += p[1024];
        }
    }
    float ig = 1.f / (1.f + expf(-iv));
    float og = 1.f / (1.f + expf(-ov));
    float ug = tanhf(uv);
    float cn = ig * ug;

    if (!leaf) {
        float wf = wx[wrow + 1536 + j];
        #pragma unroll
        for (int k = 0; k < 4; k++) {
            int ch = children[g * 4 + k];
            float fl = 0.f;
            size_t fb = (size_t)(m * 4 + k) * HID + j;
            #pragma unroll
            for (int z = 0; z < KSPLIT; z++)
                fl += f_part[(size_t)z * PS_F + fb];
            cn = fmaf(wf + fl, c[(size_t)ch * HID + j], cn);
        }
    }
    float hv = og * tanhf(cn);
    h[(size_t)g * HID + j] = hv;
    c[(size_t)g * HID + j] = cn;
    __nv_bfloat16 hh = __float2bfloat16(hv);
    h_hi[(size_t)g * HID + j] = hh;
    h_lo[(size_t)g * HID + j] = __float2bfloat16(hv - __bfloat162float(hh));
}

// ---------------------------------------------------------------------------
// Fused whole-level kernel for tiny levels (nl <= 21): one launch per level.
// grid = (16, nl); block 256. Block (jb, m) computes node s+m, hidden dims
// [jb*32, jb*32+32): reduce + U_iou@hsum + U_f@h_ch + gating, all fp32.
// Consumers of these levels are also fused -> no bf16 h needed.
// ---------------------------------------------------------------------------
__global__ __launch_bounds__(256) void fused_level_kernel(
    const float* __restrict__ wx,
    const float* __restrict__ U_iou, const float* __restrict__ U_f,
    const int* __restrict__ children,
    float* __restrict__ h, float* __restrict__ c, int s)
{
    __shared__ float sh_h[4][512];
    __shared__ float sh_hs[512];
    __shared__ float dots[224];

    const int m = blockIdx.y, jb = blockIdx.x, g = s + m;
    const int tid = threadIdx.x;
    const int wid = tid >> 5, lane = tid & 31;

    int ch[4];
    #pragma unroll
    for (int k = 0; k < 4; k++) ch[k] = children[g * 4 + k];

    for (int idx = tid; idx < 2048; idx += 256) {
        int k = idx >> 9, j = idx & 511;
        sh_h[k][j] = h[(size_t)ch[k] * HID + j];
    }
    __syncthreads();
    for (int j = tid; j < 512; j += 256)
        sh_hs[j] = sh_h[0][j] + sh_h[1][j] + sh_h[2][j] + sh_h[3][j];
    __syncthreads();

    // 224 warp-dots: d<96 -> iou (which = d/32, jj = d%32), else f (k, jj)
    for (int d = wid; d < 224; d += 8) {
        const float4* Urow;
        const float4* vec;
        if (d < 96) {
            int which = d >> 5, jj = d & 31;
            Urow = (const float4*)(U_iou + ((size_t)which * 512 + jb * 32 + jj) * KDIM);
            vec  = (const float4*)sh_hs;
        } else {
            int t = d - 96, k = t >> 5, jj = t & 31;
            Urow = (const float4*)(U_f + (size_t)(jb * 32 + jj) * KDIM);
            vec  = (const float4*)sh_h[k];
        }
        float sum = 0.f;
        #pragma unroll
        for (int t = 0; t < 4; t++) {
            float4 u4 = Urow[lane + 32 * t];
            float4 v4 = vec[lane + 32 * t];
            sum += u4.x * v4.x + u4.y * v4.y + u4.z * v4.z + u4.w * v4.w;
        }
        #pragma unroll
        for (int off = 16; off; off >>= 1)
            sum += __shfl_xor_sync(0xffffffffu, sum, off);
        if (lane == 0) dots[d] = sum;
    }
    __syncthreads();

    if (tid < 32) {
        const int jj = tid, j = jb * 32 + jj;
        size_t wrow = (size_t)g * 2048;
        float iv = wx[wrow + j]        + dots[jj];
        float ov = wx[wrow + 512 + j]  + dots[32 + jj];
        float uv = wx[wrow + 1024 + j] + dots[64 + jj];
        float wf = wx[wrow + 1536 + j];
        float ig = 1.f / (1.f + expf(-iv));
        float og = 1.f / (1.f + expf(-ov));
        float ug = tanhf(uv);
        float cn = ig * ug;
        #pragma unroll
        for (int k = 0; k < 4; k++)
            cn = fmaf(wf + dots[96 + k * 32 + jj],
                      c[(size_t)ch[k] * HID + j], cn);
        h[(size_t)g * HID + j] = og * tanhf(cn);
        c[(size_t)g * HID + j] = cn;
    }
}

// ---------------------------------------------------------------------------
// Host orchestration (graph-capturable: kernel launches only).
// ---------------------------------------------------------------------------
extern "C" void kernel_launch(void* const* d_in, const int* in_sizes, int n_in,
                              void* d_out, int out_size)
{
    const float* x        = (const float*)d_in[0];
    const int*   children = (const int*)  d_in[1];
    const float* W_iou    = (const float*)d_in[2];
    const float* b_iou    = (const float*)d_in[3];
    const float* W_f      = (const float*)d_in[4];
    const float* b_f      = (const float*)d_in[5];
    const float* U_iou    = (const float*)d_in[6];
    const float* U_f      = (const float*)d_in[7];

    float* h = (float*)d_out;
    float* c = h + (size_t)N_NODES * HID;

    static bool attr_set = false;
    if (!attr_set) {
        cudaFuncSetAttribute(gemm_bf16_split,
                             cudaFuncAttributeMaxDynamicSharedMemorySize,
                             GEMM_SMEM);
        attr_set = true;
    }

    float *wx, *iou_part, *f_part, *bias_cat;
    __nv_bfloat16 *x_hi, *x_lo, *h_hi, *h_lo, *hs_hi, *hs_lo;
    __nv_bfloat16 *Wc_hi, *Wc_lo, *Uiou_hi, *Uiou_lo, *Uf_hi, *Uf_lo;
    cudaGetSymbolAddress((void**)&wx,       g_wx);
    cudaGetSymbolAddress((void**)&iou_part, g_iou_part);
    cudaGetSymbolAddress((void**)&f_part,   g_f_part);
    cudaGetSymbolAddress((void**)&bias_cat, g_bias);
    cudaGetSymbolAddress((void**)&x_hi,     g_x_hi);
    cudaGetSymbolAddress((void**)&x_lo,     g_x_lo);
    cudaGetSymbolAddress((void**)&h_hi,     g_h_hi);
    cudaGetSymbolAddress((void**)&h_lo,     g_h_lo);
    cudaGetSymbolAddress((void**)&hs_hi,    g_hs_hi);
    cudaGetSymbolAddress((void**)&hs_lo,    g_hs_lo);
    cudaGetSymbolAddress((void**)&Wc_hi,    g_Wcat_hi);
    cudaGetSymbolAddress((void**)&Wc_lo,    g_Wcat_lo);
    cudaGetSymbolAddress((void**)&Uiou_hi,  g_Uiou_hi);
    cudaGetSymbolAddress((void**)&Uiou_lo,  g_Uiou_lo);
    cudaGetSymbolAddress((void**)&Uf_hi,    g_Uf_hi);
    cudaGetSymbolAddress((void**)&Uf_lo,    g_Uf_lo);

    // 1. zero leaf rows of h and c
    {
        const size_t leafBase = (size_t)N_INTERNAL * HID;
        const int n4 = (N_NODES - N_INTERNAL) * HID / 4;
        zero_kernel<<<1024, 256>>>((float4*)(h + leafBase), n4);
        zero_kernel<<<1024, 256>>>((float4*)(c + leafBase), n4);
    }

    // 2. splits + bias concat
    split_kernel<<<2048, 256>>>(W_iou, Wc_hi, Wc_lo, IOU3 * KDIM);
    split_kernel<<<1024, 256>>>(W_f, Wc_hi + IOU3 * KDIM, Wc_lo + IOU3 * KDIM,
                                HID * KDIM);
    split_kernel<<<2048, 256>>>(U_iou, Uiou_hi, Uiou_lo, IOU3 * HID);
    split_kernel<<<1024, 256>>>(U_f,   Uf_hi,   Uf_lo,   HID * HID);
    split_kernel<<<4096, 256>>>(x,     x_hi,    x_lo,    N_INTERNAL * KDIM);
    concat_bias_kernel<<<8, 256>>>(b_iou, b_f, bias_cat);

    // 3. merged precompute: wx[5461,2048] = x @ [W_iou;W_f]^T + [b_iou;b_f]
    {
        dim3 g(2048 / 128, (N_INTERNAL + 127) / 128, 1);
        gemm_bf16_split<<<g, 256, GEMM_SMEM>>>(x_hi, x_lo, Wc_hi, Wc_lo,
                                               bias_cat, wx, N_INTERNAL, 2048,
                                               16, 0);
    }

    static const int offs[9] = {0, 1, 5, 21, 85, 341, 1365, 5461, 21845};

    // 4. level 6: children are leaves -> pure pointwise
    epilogue_kernel<<<offs[7] - offs[6], HID>>>(wx, nullptr, nullptr, children,
                                                h, c, h_hi, h_lo, offs[6], 1);

    // 5. levels 5,4: split-K MMA GEMMs + partial-summing epilogue
    for (int l = 5; l >= 4; --l) {
        int s  = offs[l];
        int nl = offs[l + 1] - s;
        int cs = offs[l + 1];
        int mf = 4 * nl;

        dim3 gf(HID / 128, (mf + 127) / 128, KSPLIT);
        gemm_bf16_split<<<gf, 256, GEMM_SMEM>>>(h_hi + (size_t)cs * HID,
                                                h_lo + (size_t)cs * HID,
                                                Uf_hi, Uf_lo, nullptr, f_part,
                                                mf, HID, 16 / KSPLIT, PS_F);

        reduce4_split_kernel<<<nl, HID>>>(h, children, hs_hi, hs_lo, s);

        dim3 gi(IOU3 / 128, (nl + 127) / 128, KSPLIT);
        gemm_bf16_split<<<gi, 256, GEMM_SMEM>>>(hs_hi, hs_lo, Uiou_hi, Uiou_lo,
                                                nullptr, iou_part, nl, IOU3,
                                                16 / KSPLIT, PS_IOU);

        epilogue_kernel<<<nl, HID>>>(wx, iou_part, f_part, children,
                                     h, c, h_hi, h_lo, s, 0);
    }

    // 6. levels 3..0: fully fused, one launch per level (fp32 exact)
    for (int l = 3; l >= 0; --l) {
        int s  = offs[l];
        int nl = offs[l + 1] - s;
        dim3 g(16, nl);
        fused_level_kernel<<<g, 256>>>(wx, U_iou, U_f, children, h, c, s);
    }
}

// round 16
// speedup vs baseline: 3.9239x; 1.0711x over previous
#include <cuda_runtime.h>
#include <cuda_bf16.h>
#include <cstdint>
#include <cstdio>

// ---------------------------------------------------------------------------
// Child-Sum Tree-LSTM, complete 4-ary tree. B=4, DEPTH=7.
// N_NODES=21845, N_INTERNAL=5461, HID=512, IOU3=1536, K=512.
//
// R16 == R14 resubmitted (R15 bench was an infra failure, kernel unmeasured):
// 2-stage cp.async pipeline (80KB smem) -> 2 CTAs/SM on the GEMM
// (was 3-stage/122KB/1 CTA -> only 2 warps/SMSP, exposed bubbles).
// Merged prep (all hi/lo splits + bias concat) and merged zero kernel.
// L4 epilogue skips bf16 h emission (consumers are fp32 fused levels).
// ---------------------------------------------------------------------------

#define N_NODES     21845
#define N_INTERNAL  5461
#define HID         512
#define IOU3        1536
#define KDIM        512
#define KSPLIT      4
#define PS_IOU      (1024 * 1536)    // level-5 iou partial: M up to 1024
#define PS_F        (4096 * 512)     // level-5 f partial:   M up to 4096

// ---------------- scratch (__device__ globals; allocation-free rule) -------
__device__ __align__(16) float g_wx      [N_INTERNAL * 2048];     // [iou|f]
__device__ __align__(16) float g_iou_part[KSPLIT * PS_IOU];
__device__ __align__(16) float g_f_part  [KSPLIT * PS_F];
__device__ __align__(16) float g_bias    [2048];

__device__ __align__(16) __nv_bfloat16 g_x_hi [N_INTERNAL * KDIM];
__device__ __align__(16) __nv_bfloat16 g_x_lo [N_INTERNAL * KDIM];
__device__ __align__(16) __nv_bfloat16 g_h_hi [N_INTERNAL * HID];
__device__ __align__(16) __nv_bfloat16 g_h_lo [N_INTERNAL * HID];
__device__ __align__(16) __nv_bfloat16 g_hs_hi[1024 * HID];
__device__ __align__(16) __nv_bfloat16 g_hs_lo[1024 * HID];

__device__ __align__(16) __nv_bfloat16 g_Wcat_hi[2048 * KDIM];    // [W_iou;W_f]
__device__ __align__(16) __nv_bfloat16 g_Wcat_lo[2048 * KDIM];
__device__ __align__(16) __nv_bfloat16 g_Uiou_hi[IOU3 * HID];
__device__ __align__(16) __nv_bfloat16 g_Uiou_lo[IOU3 * HID];
__device__ __align__(16) __nv_bfloat16 g_Uf_hi  [HID * HID];
__device__ __align__(16) __nv_bfloat16 g_Uf_lo  [HID * HID];

// ---------------------------------------------------------------------------
// PTX helpers (plain-sm_103-legal)
// ---------------------------------------------------------------------------
__device__ __forceinline__ uint32_t smem_u32(const void* ptr) {
    uint32_t a;
    asm("{ .reg .u64 t; cvta.to.shared.u64 t, %1; cvt.u32.u64 %0, t; }"
        : "=r"(a) : "l"(ptr));
    return a;
}
__device__ __forceinline__ void cp16(uint32_t s, const void* g, bool valid) {
    int sz = valid ? 16 : 0;
    asm volatile("cp.async.cg.shared.global [%0], [%1], 16, %2;"
                 :: "r"(s), "l"(g), "r"(sz));
}
#define CP_COMMIT() asm volatile("cp.async.commit_group;")
template <int N>
__device__ __forceinline__ void cp_wait() {
    asm volatile("cp.async.wait_group %0;" :: "n"(N));
}
#define LDMX4(r, addr) \
    asm volatile("ldmatrix.sync.aligned.m8n8.x4.shared.b16 {%0,%1,%2,%3}, [%4];" \
        : "=r"((r)[0]), "=r"((r)[1]), "=r"((r)[2]), "=r"((r)[3]) : "r"(addr))
#define MMA_BF16(d, a, b0v, b1v) \
    asm volatile("mma.sync.aligned.m16n8k16.row.col.f32.bf16.bf16.f32 " \
        "{%0,%1,%2,%3}, {%4,%5,%6,%7}, {%8,%9}, {%0,%1,%2,%3};" \
        : "+f"((d)[0]), "+f"((d)[1]), "+f"((d)[2]), "+f"((d)[3]) \
        : "r"((a)[0]), "r"((a)[1]), "r"((a)[2]), "r"((a)[3]), \
          "r"(b0v), "r"(b1v))

// ---------------------------------------------------------------------------
// GEMM: C[M,N] (+bias) = (Ahi+Alo)[M,512] @ (Bhi+Blo)[N,512]^T, 3-term split.
// CTA 128x128, 8 warps (64x32), K-chunk 32, 2-stage cp.async, 2 CTAs/SM.
// blockIdx.z = K-split; split z handles chunks [z*cpz, (z+1)*cpz) and writes
// C + z*zstride (zstride=0 for unsplit launches).
// ---------------------------------------------------------------------------
#define ROWB        80
#define OFF_AH      0
#define OFF_AL      10240
#define OFF_BH      20480
#define OFF_BL      30720
#define STAGE_BYTES 40960
#define GEMM_SMEM   (2 * STAGE_BYTES)    // 81920 -> 2 CTAs/SM

__global__ __launch_bounds__(256, 2) void gemm_bf16_split(
    const __nv_bfloat16* __restrict__ Ahi, const __nv_bfloat16* __restrict__ Alo,
    const __nv_bfloat16* __restrict__ Bhi, const __nv_bfloat16* __restrict__ Blo,
    const float* __restrict__ bias, float* __restrict__ C, int M, int N,
    int cpz, size_t zstride)
{
    extern __shared__ char smem[];
    const uint32_t sb = smem_u32(smem);

    const int tid  = threadIdx.x;
    const int wid  = tid >> 5;
    const int lane = tid & 31;
    const int wm   = wid >> 2;
    const int wn   = wid & 3;
    const int brow = blockIdx.y * 128;
    const int bcol = blockIdx.x * 128;
    const int c0   = blockIdx.z * cpz;

    const int srow = tid >> 1;
    const int scol = (tid & 1) * 16;
    const uint32_t soff = (uint32_t)(srow * ROWB + scol * 2);
    const bool a_ok = (brow + srow) < M;

    const __nv_bfloat16* gAh = Ahi + (size_t)(brow + srow) * KDIM + scol;
    const __nv_bfloat16* gAl = Alo + (size_t)(brow + srow) * KDIM + scol;
    const __nv_bfloat16* gBh = Bhi + (size_t)(bcol + srow) * KDIM + scol;
    const __nv_bfloat16* gBl = Blo + (size_t)(bcol + srow) * KDIM + scol;

    auto prefetch = [&](int chunk, int st) {
        const uint32_t base = sb + (uint32_t)st * STAGE_BYTES + soff;
        const int k0 = chunk * 32;
        cp16(base + OFF_AH,      gAh + k0,     a_ok);
        cp16(base + OFF_AH + 16, gAh + k0 + 8, a_ok);
        cp16(base + OFF_AL,      gAl + k0,     a_ok);
        cp16(base + OFF_AL + 16, gAl + k0 + 8, a_ok);
        cp16(base + OFF_BH,      gBh + k0,     true);
        cp16(base + OFF_BH + 16, gBh + k0 + 8, true);
        cp16(base + OFF_BL,      gBl + k0,     true);
        cp16(base + OFF_BL + 16, gBl + k0 + 8, true);
        CP_COMMIT();
    };

    float acc[4][4][4];
    #pragma unroll
    for (int i = 0; i < 4; i++)
        #pragma unroll
        for (int j = 0; j < 4; j++)
            #pragma unroll
            for (int k = 0; k < 4; k++) acc[i][j][k] = 0.f;

    const uint32_t fr_row = (uint32_t)(lane & 15);
    const uint32_t fr_kof = (uint32_t)((lane >> 4) * 8);

    prefetch(c0, 0);

    for (int i = 0; i < cpz; i++) {
        // prefetch i+1 into the buffer last computed at i-1 (sync'd below)
        if (i + 1 < cpz) { prefetch(c0 + i + 1, (i + 1) & 1); cp_wait<1>(); }
        else             { cp_wait<0>(); }
        __syncthreads();

        const uint32_t base = sb + (uint32_t)(i & 1) * STAGE_BYTES;
        #pragma unroll
        for (int kt = 0; kt < 2; kt++) {
            const uint32_t kbyte = (uint32_t)((kt * 16 + fr_kof) * 2);
            uint32_t ah[4][4], al[4][4];
            #pragma unroll
            for (int mt = 0; mt < 4; mt++) {
                uint32_t row = (uint32_t)(wm * 64 + mt * 16) + fr_row;
                uint32_t ad = base + OFF_AH + row * ROWB + kbyte;
                LDMX4(ah[mt], ad);
                LDMX4(al[mt], ad + (OFF_AL - OFF_AH));
            }
            uint32_t bh[2][4], bl[2][4];
            #pragma unroll
            for (int nc = 0; nc < 2; nc++) {
                uint32_t row = (uint32_t)(wn * 32 + nc * 16) + fr_row;
                uint32_t ad = base + OFF_BH + row * ROWB + kbyte;
                LDMX4(bh[nc], ad);
                LDMX4(bl[nc], ad + (OFF_BL - OFF_BH));
            }
            #pragma unroll
            for (int mt = 0; mt < 4; mt++)
                #pragma unroll
                for (int nc = 0; nc < 2; nc++)
                    #pragma unroll
                    for (int sub = 0; sub < 2; sub++) {
                        float* d = acc[mt][nc * 2 + sub];
                        MMA_BF16(d, ah[mt], bh[nc][sub], bh[nc][sub + 2]);
                        MMA_BF16(d, ah[mt], bl[nc][sub], bl[nc][sub + 2]);
                        MMA_BF16(d, al[mt], bh[nc][sub], bh[nc][sub + 2]);
                    }
        }
        __syncthreads();   // stage i free for re-prefetch next iteration
    }

    float* Cz = C + (size_t)blockIdx.z * zstride;
    const int erow = lane >> 2;
    const int ecol = (lane & 3) * 2;
    #pragma unroll
    for (int mt = 0; mt < 4; mt++) {
        const int r0 = brow + wm * 64 + mt * 16 + erow;
        #pragma unroll
        for (int nt = 0; nt < 4; nt++) {
            const int cc = bcol + wn * 32 + nt * 8 + ecol;
            float b0 = 0.f, b1 = 0.f;
            if (bias) { b0 = bias[cc]; b1 = bias[cc + 1]; }
            if (r0 < M) {
                float2 v = make_float2(acc[mt][nt][0] + b0, acc[mt][nt][1] + b1);
                *(float2*)(Cz + (size_t)r0 * N + cc) = v;
            }
            if (r0 + 8 < M) {
                float2 v = make_float2(acc[mt][nt][2] + b0, acc[mt][nt][3] + b1);
                *(float2*)(Cz + (size_t)(r0 + 8) * N + cc) = v;
            }
        }
    }
}

// ---------------------------------------------------------------------------
// prep: ALL fp32->bf16 hi/lo splits + bias concat in ONE launch.
// Segment boundaries are compile-time constants.
// ---------------------------------------------------------------------------
#define SEG0 (IOU3 * KDIM)                  // W_iou   786432
#define SEG1 (SEG0 + HID * KDIM)            // W_f    1048576
#define SEG2 (SEG1 + IOU3 * HID)            // U_iou  1835008
#define SEG3 (SEG2 + HID * HID)             // U_f    2097152
#define SEG4 (SEG3 + N_INTERNAL * KDIM)     // x      4893184
#define SEG5 (SEG4 + 2048)                  // bias   4895232

__global__ void prep_kernel(const float* __restrict__ W_iou,
                            const float* __restrict__ W_f,
                            const float* __restrict__ U_iou,
                            const float* __restrict__ U_f,
                            const float* __restrict__ x,
                            const float* __restrict__ b_iou,
                            const float* __restrict__ b_f,
                            __nv_bfloat16* __restrict__ Wc_hi,
                            __nv_bfloat16* __restrict__ Wc_lo,
                            __nv_bfloat16* __restrict__ Uiou_hi,
                            __nv_bfloat16* __restrict__ Uiou_lo,
                            __nv_bfloat16* __restrict__ Uf_hi,
                            __nv_bfloat16* __restrict__ Uf_lo,
                            __nv_bfloat16* __restrict__ x_hi,
                            __nv_bfloat16* __restrict__ x_lo,
                            float* __restrict__ bias)
{
    int i = blockIdx.x * blockDim.x + threadIdx.x;
    int st = gridDim.x * blockDim.x;
    for (; i < SEG5; i += st) {
        if (i >= SEG4) {                      // bias concat (float out)
            int j = i - SEG4;
            bias[j] = (j < IOU3) ? b_iou[j] : b_f[j - IOU3];
            continue;
        }
        const float* src;
        __nv_bfloat16 *hi, *lo;
        int j;
        if (i < SEG0)      { j = i;        src = W_iou; hi = Wc_hi;        lo = Wc_lo; }
        else if (i < SEG1) { j = i - SEG0; src = W_f;   hi = Wc_hi + SEG0; lo = Wc_lo + SEG0; }
        else if (i < SEG2) { j = i - SEG1; src = U_iou; hi = Uiou_hi;      lo = Uiou_lo; }
        else if (i < SEG3) { j = i - SEG2; src = U_f;   hi = Uf_hi;        lo = Uf_lo; }
        else               { j = i - SEG3; src = x;     hi = x_hi;         lo = x_lo; }
        float v = src[j];
        __nv_bfloat16 h = __float2bfloat16(v);
        hi[j] = h;
        lo[j] = __float2bfloat16(v - __bfloat162float(h));
    }
}

// ---------------------------------------------------------------------------
// zero both leaf regions (h leaves + c leaves) in one launch
// ---------------------------------------------------------------------------
__global__ void zero2_kernel(float4* __restrict__ p1, float4* __restrict__ p2,
                             int n4)
{
    int i = blockIdx.x * blockDim.x + threadIdx.x;
    int st = gridDim.x * blockDim.x;
    float4 z = make_float4(0.f, 0.f, 0.f, 0.f);
    for (; i < 2 * n4; i += st) {
        if (i < n4) p1[i] = z;
        else        p2[i - n4] = z;
    }
}

// ---------------------------------------------------------------------------
// h_sum over 4 children -> bf16 hi/lo
// ---------------------------------------------------------------------------
__global__ void reduce4_split_kernel(const float* __restrict__ h,
                                     const int* __restrict__ children,
                                     __nv_bfloat16* __restrict__ hs_hi,
                                     __nv_bfloat16* __restrict__ hs_lo, int s)
{
    int m = blockIdx.x, j = threadIdx.x, g = s + m;
    float v = 0.f;
    #pragma unroll
    for (int k = 0; k < 4; k++) {
        int ch = children[g * 4 + k];
        v += h[(size_t)ch * HID + j];
    }
    __nv_bfloat16 hh = __float2bfloat16(v);
    hs_hi[(size_t)m * HID + j] = hh;
    hs_lo[(size_t)m * HID + j] = __float2bfloat16(v - __bfloat162float(hh));
}

// ---------------------------------------------------------------------------
// Gated epilogue (levels 6,5,4). Sums KSPLIT GEMM partials when !leaf.
// wx layout: row g, cols [0:512)=i, [512:1024)=o, [1024:1536)=u, [1536:2048)=wf.
// NO sigmoid on f (matches reference). h_hi==null -> skip bf16 emission.
// ---------------------------------------------------------------------------
__global__ void epilogue_kernel(const float* __restrict__ wx,
                                const float* __restrict__ iou_part,
                                const float* __restrict__ f_part,
                                const int* __restrict__ children,
                                float* __restrict__ h, float* __restrict__ c,
                                __nv_bfloat16* __restrict__ h_hi,
                                __nv_bfloat16* __restrict__ h_lo,
                                int s, int leaf)
{
    int m = blockIdx.x, j = threadIdx.x, g = s + m;

    size_t wrow = (size_t)g * 2048;
    float iv = wx[wrow + j];
    float ov = wx[wrow + 512 + j];
    float uv = wx[wrow + 1024 + j];
    if (!leaf) {
        size_t lb = (size_t)m * IOU3 + j;
        #pragma unroll
        for (int z = 0; z < KSPLIT; z++) {
            const float* p = iou_part + (size_t)z * PS_IOU + lb;
            iv += p[0]; ov += p[512]; uv += p[1024];
        }
    }
    float ig = 1.f / (1.f + expf(-iv));
    float og = 1.f / (1.f + expf(-ov));
    float ug = tanhf(uv);
    float cn = ig * ug;

    if (!leaf) {
        float wf = wx[wrow + 1536 + j];
        #pragma unroll
        for (int k = 0; k < 4; k++) {
            int ch = children[g * 4 + k];
            float fl = 0.f;
            size_t fb = (size_t)(m * 4 + k) * HID + j;
            #pragma unroll
            for (int z = 0; z < KSPLIT; z++)
                fl += f_part[(size_t)z * PS_F + fb];
            cn = fmaf(wf + fl, c[(size_t)ch * HID + j], cn);
        }
    }
    float hv = og * tanhf(cn);
    h[(size_t)g * HID + j] = hv;
    c[(size_t)g * HID + j] = cn;
    if (h_hi) {
        __nv_bfloat16 hh = __float2bfloat16(hv);
        h_hi[(size_t)g * HID + j] = hh;
        h_lo[(size_t)g * HID + j] = __float2bfloat16(hv - __bfloat162float(hh));
    }
}

// ---------------------------------------------------------------------------
// Fused whole-level kernel for tiny levels (nl <= 21): one launch per level.
// grid = (16, nl); block 256. Block (jb, m) computes node s+m, hidden dims
// [jb*32, jb*32+32): reduce + U_iou@hsum + U_f@h_ch + gating, all fp32.
// ---------------------------------------------------------------------------
__global__ __launch_bounds__(256) void fused_level_kernel(
    const float* __restrict__ wx,
    const float* __restrict__ U_iou, const float* __restrict__ U_f,
    const int* __restrict__ children,
    float* __restrict__ h, float* __restrict__ c, int s)
{
    __shared__ float sh_h[4][512];
    __shared__ float sh_hs[512];
    __shared__ float dots[224];

    const int m = blockIdx.y, jb = blockIdx.x, g = s + m;
    const int tid = threadIdx.x;
    const int wid = tid >> 5, lane = tid & 31;

    int ch[4];
    #pragma unroll
    for (int k = 0; k < 4; k++) ch[k] = children[g * 4 + k];

    for (int idx = tid; idx < 2048; idx += 256) {
        int k = idx >> 9, j = idx & 511;
        sh_h[k][j] = h[(size_t)ch[k] * HID + j];
    }
    __syncthreads();
    for (int j = tid; j < 512; j += 256)
        sh_hs[j] = sh_h[0][j] + sh_h[1][j] + sh_h[2][j] + sh_h[3][j];
    __syncthreads();

    // 224 warp-dots: d<96 -> iou (which = d/32, jj = d%32), else f (k, jj)
    for (int d = wid; d < 224; d += 8) {
        const float4* Urow;
        const float4* vec;
        if (d < 96) {
            int which = d >> 5, jj = d & 31;
            Urow = (const float4*)(U_iou + ((size_t)which * 512 + jb * 32 + jj) * KDIM);
            vec  = (const float4*)sh_hs;
        } else {
            int t = d - 96, k = t >> 5, jj = t & 31;
            Urow = (const float4*)(U_f + (size_t)(jb * 32 + jj) * KDIM);
            vec  = (const float4*)sh_h[k];
        }
        float sum = 0.f;
        #pragma unroll
        for (int t = 0; t < 4; t++) {
            float4 u4 = Urow[lane + 32 * t];
            float4 v4 = vec[lane + 32 * t];
            sum += u4.x * v4.x + u4.y * v4.y + u4.z * v4.z + u4.w * v4.w;
        }
        #pragma unroll
        for (int off = 16; off; off >>= 1)
            sum += __shfl_xor_sync(0xffffffffu, sum, off);
        if (lane == 0) dots[d] = sum;
    }
    __syncthreads();

    if (tid < 32) {
        const int jj = tid, j = jb * 32 + jj;
        size_t wrow = (size_t)g * 2048;
        float iv = wx[wrow + j]        + dots[jj];
        float ov = wx[wrow + 512 + j]  + dots[32 + jj];
        float uv = wx[wrow + 1024 + j] + dots[64 + jj];
        float wf = wx[wrow + 1536 + j];
        float ig = 1.f / (1.f + expf(-iv));
        float og = 1.f / (1.f + expf(-ov));
        float ug = tanhf(uv);
        float cn = ig * ug;
        #pragma unroll
        for (int k = 0; k < 4; k++)
            cn = fmaf(wf + dots[96 + k * 32 + jj],
                      c[(size_t)ch[k] * HID + j], cn);
        h[(size_t)g * HID + j] = og * tanhf(cn);
        c[(size_t)g * HID + j] = cn;
    }
}

// ---------------------------------------------------------------------------
// Host orchestration (graph-capturable: kernel launches only).
// ---------------------------------------------------------------------------
extern "C" void kernel_launch(void* const* d_in, const int* in_sizes, int n_in,
                              void* d_out, int out_size)
{
    const float* x        = (const float*)d_in[0];
    const int*   children = (const int*)  d_in[1];
    const float* W_iou    = (const float*)d_in[2];
    const float* b_iou    = (const float*)d_in[3];
    const float* W_f      = (const float*)d_in[4];
    const float* b_f      = (const float*)d_in[5];
    const float* U_iou    = (const float*)d_in[6];
    const float* U_f      = (const float*)d_in[7];

    float* h = (float*)d_out;
    float* c = h + (size_t)N_NODES * HID;

    static bool attr_set = false;
    if (!attr_set) {
        cudaFuncSetAttribute(gemm_bf16_split,
                             cudaFuncAttributeMaxDynamicSharedMemorySize,
                             GEMM_SMEM);
        attr_set = true;
    }

    float *wx, *iou_part, *f_part, *bias_cat;
    __nv_bfloat16 *x_hi, *x_lo, *h_hi, *h_lo, *hs_hi, *hs_lo;
    __nv_bfloat16 *Wc_hi, *Wc_lo, *Uiou_hi, *Uiou_lo, *Uf_hi, *Uf_lo;
    cudaGetSymbolAddress((void**)&wx,       g_wx);
    cudaGetSymbolAddress((void**)&iou_part, g_iou_part);
    cudaGetSymbolAddress((void**)&f_part,   g_f_part);
    cudaGetSymbolAddress((void**)&bias_cat, g_bias);
    cudaGetSymbolAddress((void**)&x_hi,     g_x_hi);
    cudaGetSymbolAddress((void**)&x_lo,     g_x_lo);
    cudaGetSymbolAddress((void**)&h_hi,     g_h_hi);
    cudaGetSymbolAddress((void**)&h_lo,     g_h_lo);
    cudaGetSymbolAddress((void**)&hs_hi,    g_hs_hi);
    cudaGetSymbolAddress((void**)&hs_lo,    g_hs_lo);
    cudaGetSymbolAddress((void**)&Wc_hi,    g_Wcat_hi);
    cudaGetSymbolAddress((void**)&Wc_lo,    g_Wcat_lo);
    cudaGetSymbolAddress((void**)&Uiou_hi,  g_Uiou_hi);
    cudaGetSymbolAddress((void**)&Uiou_lo,  g_Uiou_lo);
    cudaGetSymbolAddress((void**)&Uf_hi,    g_Uf_hi);
    cudaGetSymbolAddress((void**)&Uf_lo,    g_Uf_lo);

    // 1. zero leaf rows of h and c (one launch)
    {
        const size_t leafBase = (size_t)N_INTERNAL * HID;
        const int n4 = (N_NODES - N_INTERNAL) * HID / 4;
        zero2_kernel<<<2048, 256>>>((float4*)(h + leafBase),
                                    (float4*)(c + leafBase), n4);
    }

    // 2. all splits + bias concat (one launch)
    prep_kernel<<<4096, 256>>>(W_iou, W_f, U_iou, U_f, x, b_iou, b_f,
                               Wc_hi, Wc_lo, Uiou_hi, Uiou_lo, Uf_hi, Uf_lo,
                               x_hi, x_lo, bias_cat);

    // 3. merged precompute: wx[5461,2048] = x @ [W_iou;W_f]^T + [b_iou;b_f]
    {
        dim3 g(2048 / 128, (N_INTERNAL + 127) / 128, 1);
        gemm_bf16_split<<<g, 256, GEMM_SMEM>>>(x_hi, x_lo, Wc_hi, Wc_lo,
                                               bias_cat, wx, N_INTERNAL, 2048,
                                               16, 0);
    }

    static const int offs[9] = {0, 1, 5, 21, 85, 341, 1365, 5461, 21845};

    // 4. level 6: children are leaves -> pure pointwise
    epilogue_kernel<<<offs[7] - offs[6], HID>>>(wx, nullptr, nullptr, children,
                                                h, c, h_hi, h_lo, offs[6], 1);

    // 5. levels 5,4: split-K MMA GEMMs + partial-summing epilogue
    for (int l = 5; l >= 4; --l) {
        int s  = offs[l];
        int nl = offs[l + 1] - s;
        int cs = offs[l + 1];
        int mf = 4 * nl;

        dim3 gf(HID / 128, (mf + 127) / 128, KSPLIT);
        gemm_bf16_split<<<gf, 256, GEMM_SMEM>>>(h_hi + (size_t)cs * HID,
                                                h_lo + (size_t)cs * HID,
                                                Uf_hi, Uf_lo, nullptr, f_part,
                                                mf, HID, 16 / KSPLIT, PS_F);

        reduce4_split_kernel<<<nl, HID>>>(h, children, hs_hi, hs_lo, s);

        dim3 gi(IOU3 / 128, (nl + 127) / 128, KSPLIT);
        gemm_bf16_split<<<gi, 256, GEMM_SMEM>>>(hs_hi, hs_lo, Uiou_hi, Uiou_lo,
                                                nullptr, iou_part, nl, IOU3,
                                                16 / KSPLIT, PS_IOU);

        // L4 epilogue: consumers (fused levels) read fp32 h -> skip bf16 emit
        __nv_bfloat16* eh = (l == 5) ? h_hi : nullptr;
        __nv_bfloat16* el = (l == 5) ? h_lo : nullptr;
        epilogue_kernel<<<nl, HID>>>(wx, iou_part, f_part, children,
                                     h, c, eh, el, s, 0);
    }

    // 6. levels 3..0: fully fused, one launch per level (fp32 exact)
    for (int l = 3; l >= 0; --l) {
        int s  = offs[l];
        int nl = offs[l + 1] - s;
        dim3 g(16, nl);
        fused_level_kernel<<<g, 256>>>(wx, U_iou, U_f, children, h, c, s);
    }
}